// round 12
// baseline (speedup 1.0000x reference)
#include <cuda_runtime.h>
#include <cuda_fp16.h>
#include <math.h>
#include <stdint.h>

#define NPTS 1024
#define NH   16
#define ASTRIDE 144   // bytes per SMEM tile row: 64 fp16 = 128B + 16B pad (conflict-free)
#define TPB  256

static __device__ __forceinline__ uint32_t smem_addr(const void* p) {
    return (uint32_t)__cvta_generic_to_shared(p);
}

static __device__ __forceinline__ void ldsm_x4(uint32_t& r0, uint32_t& r1,
                                               uint32_t& r2, uint32_t& r3, uint32_t a) {
    asm volatile("ldmatrix.sync.aligned.m8n8.x4.shared.b16 {%0,%1,%2,%3}, [%4];"
                 : "=r"(r0), "=r"(r1), "=r"(r2), "=r"(r3) : "r"(a));
}

static __device__ __forceinline__ void mma16816(float& d0, float& d1, float& d2, float& d3,
                                                uint32_t a0, uint32_t a1, uint32_t a2, uint32_t a3,
                                                uint32_t b0, uint32_t b1) {
    asm volatile("mma.sync.aligned.m16n8k16.row.col.f32.f16.f16.f32 "
                 "{%0,%1,%2,%3}, {%4,%5,%6,%7}, {%8,%9}, {%0,%1,%2,%3};"
                 : "+f"(d0), "+f"(d1), "+f"(d2), "+f"(d3)
                 : "r"(a0), "r"(a1), "r"(a2), "r"(a3), "r"(b0), "r"(b1));
}

// round-to-nearest-even via magic number (valid for |x| < 2^22)
static __device__ __forceinline__ float rne(float x) {
    return (x + 12582912.0f) - 12582912.0f;
}

// Fused kernel. grid = (1024 rows i, 2 d-blocks, B); block = 256 threads.
// Thread tid generates fp16 features for pair (i, j), j = (i + dbase + tid + 1) mod 1024,
// into padded SMEM row tid via 4 interleaved rotation chains (k = 4s + c, step 4*tr).
// One early block barrier (weights); then each warp: __syncwarp -> ldmatrix -> HMMA -> stores.
// Covers every off-diagonal unordered pair once (distance-512 twice, bitwise identical);
// writes out[i,j,:] and out[j,i,:]. Diagonal by d-block 0. Bias lives in the accumulators.
__global__ __launch_bounds__(TPB)
void relbias_kernel(const float* __restrict__ vec,  // [B,1024,3]
                    const float* __restrict__ W,    // [64,16]
                    const float* __restrict__ bias, // [16]
                    float* __restrict__ out) {
    __shared__ __align__(16) uint8_t sA[TPB * ASTRIDE]; // fp16 features, row = pair
    __shared__ __align__(16) uint8_t sW[16 * ASTRIDE];  // fp16 weights [n][f']

    int tid = threadIdx.x;
    int i     = blockIdx.x;
    int dbase = blockIdx.y << 8;
    int b     = blockIdx.z;
    long long bb = (long long)b * NPTS;

    // W[64,16] fp32 -> sW[n][f'] fp16, f' interleaved: f'=2k -> Ws[k], f'=2k+1 -> Wc[k]
    for (int idx = tid; idx < 64 * 16; idx += TPB) {
        int n = idx & 15, k = idx >> 4;
        int fp = (k < 32) ? (2 * k) : (2 * (k - 32) + 1);
        *(__half*)(sW + n * ASTRIDE + fp * 2) = __float2half_rn(W[idx]);
    }
    // diagonal (exact fp32): out[b,i,i,:] = bias + sum_k Wc[k,:]
    if (blockIdx.y == 0 && tid < NH) {
        float a = bias[tid];
#pragma unroll
        for (int k = 0; k < 32; ++k) a += W[(32 + k) * NH + tid];
        out[((bb + i) * NPTS + i) * NH + tid] = a;
    }
    __syncthreads();   // the ONLY block-wide barrier (sW ready)

    // ---- per-thread pair: angle ----
    int j = (i + dbase + tid + 1) & (NPTS - 1);
    const float* vb = vec + (size_t)b * NPTS * 3;
    float ax = vb[i * 3 + 0], ay = vb[i * 3 + 1], az = vb[i * 3 + 2];
    float bx = vb[j * 3 + 0], by = vb[j * 3 + 1], bz = vb[j * 3 + 2];
    float ra = rsqrtf(ax * ax + ay * ay + az * az);
    float rb = rsqrtf(bx * bx + by * by + bz * bz);
    float dx = ax * ra - bx * rb;
    float dy = ay * ra - by * rb;
    float dz = az * ra - bz * rb;
    float dot = 1.0f - 0.5f * ((dx * dx + dy * dy) + dz * dz);
    dot = fminf(fmaxf(dot, -1.0f), 1.0f);
    float t = acosf(dot) * 200.0f * (10.0f / 31.0f);

    // fp32 Cody-Waite mod 2*pi (magic-number rounding)
    float q  = rne(t * 0.15915494309189535f);
    float tr = fmaf(q, -6.28125f, t);
    tr = fmaf(q, -1.9353071795864769e-3f, tr);
    float s1 = __sinf(tr), c1 = __cosf(tr);

    // anchors for 4 chains via angle-addition (one MUFU pair total)
    float s2 = 2.0f * s1 * c1;
    float c2 = fmaf(-2.0f * s1, s1, 1.0f);
    float s3 = fmaf(s1, c2, c1 * s2);
    float c3 = fmaf(c1, c2, -(s1 * s2));
    float s4 = 2.0f * s2 * c2;                 // step rot = 4*tr
    float c4s = fmaf(-2.0f * s2, s2, 1.0f);

    float S0 = 0.0f, C0 = 1.0f;
    float S1 = s1,   C1 = c1;
    float S2 = s2,   C2 = c2;
    float S3 = s3,   C3 = c3;

    // ---- feature gen: 8 steps, one STS.128 each (immediate offsets); 4 chains ----
    {
        uint32_t base_t = smem_addr(sA) + (uint32_t)tid * ASTRIDE;
#pragma unroll
        for (int s = 0; s < 8; ++s) {
            __half2 h0 = __floats2half2_rn(S0, C0);
            __half2 h1 = __floats2half2_rn(S1, C1);
            __half2 h2h = __floats2half2_rn(S2, C2);
            __half2 h3 = __floats2half2_rn(S3, C3);
            asm volatile("st.shared.v4.b32 [%0], {%1,%2,%3,%4};"
                         :: "r"(base_t + (uint32_t)s * 16u),
                            "r"(*(uint32_t*)&h0), "r"(*(uint32_t*)&h1),
                            "r"(*(uint32_t*)&h2h), "r"(*(uint32_t*)&h3) : "memory");
            float nS0 = fmaf(S0, c4s, C0 * s4); float nC0 = fmaf(C0, c4s, -(S0 * s4));
            float nS1 = fmaf(S1, c4s, C1 * s4); float nC1 = fmaf(C1, c4s, -(S1 * s4));
            float nS2 = fmaf(S2, c4s, C2 * s4); float nC2 = fmaf(C2, c4s, -(S2 * s4));
            float nS3 = fmaf(S3, c4s, C3 * s4); float nC3 = fmaf(C3, c4s, -(S3 * s4));
            S0 = nS0; C0 = nC0; S1 = nS1; C1 = nC1;
            S2 = nS2; C2 = nC2; S3 = nS3; C3 = nC3;
        }
    }

    __syncwarp();   // warp-local: this warp's 32 A-rows are ready

    // ---- HMMA: each warp computes its own 32 pairs x 16 heads ----
    int wid = tid >> 5, lane = tid & 31;
    int wbase = wid << 5;
    int c4 = lane & 3;

    // B fragments from sW: bfrag[ntile][ktile][2]
    uint32_t bfrag[2][4][2];
    uint32_t sWb = smem_addr(sW);
#pragma unroll
    for (int nt = 0; nt < 2; ++nt) {
#pragma unroll
        for (int ktp = 0; ktp < 2; ++ktp) {
            uint32_t a = sWb + (uint32_t)(nt * 8 + (lane & 7)) * ASTRIDE
                       + (uint32_t)ktp * 64 + (uint32_t)(lane >> 3) * 16;
            ldsm_x4(bfrag[nt][2 * ktp][0], bfrag[nt][2 * ktp][1],
                    bfrag[nt][2 * ktp + 1][0], bfrag[nt][2 * ktp + 1][1], a);
        }
    }

    // accumulators initialized with bias (acc[mt][nt][e] -> head col nt*8 + 2*c4 + (e&1))
    float2 bz0 = *(const float2*)(bias + 2 * c4);
    float2 bz1 = *(const float2*)(bias + 8 + 2 * c4);
    float acc[2][2][4];
#pragma unroll
    for (int mt = 0; mt < 2; ++mt) {
        acc[mt][0][0] = bz0.x; acc[mt][0][1] = bz0.y;
        acc[mt][0][2] = bz0.x; acc[mt][0][3] = bz0.y;
        acc[mt][1][0] = bz1.x; acc[mt][1][1] = bz1.y;
        acc[mt][1][2] = bz1.x; acc[mt][1][3] = bz1.y;
    }

    uint32_t sAb = smem_addr(sA);
#pragma unroll
    for (int mt = 0; mt < 2; ++mt) {
#pragma unroll
        for (int kt = 0; kt < 4; ++kt) {
            uint32_t a = sAb + (uint32_t)(wbase + mt * 16 + (lane & 15)) * ASTRIDE
                       + (uint32_t)kt * 32 + (uint32_t)(lane >> 4) * 16;
            uint32_t a0, a1, a2, a3;
            ldsm_x4(a0, a1, a2, a3, a);
#pragma unroll
            for (int nt = 0; nt < 2; ++nt)
                mma16816(acc[mt][nt][0], acc[mt][nt][1], acc[mt][nt][2], acc[mt][nt][3],
                         a0, a1, a2, a3, bfrag[nt][kt][0], bfrag[nt][kt][1]);
        }
    }

    // ---- epilogue: bfly-shuffle into float4, symmetric STG.128 ----
    int colbase = (c4 & 1) * 8 + (c4 & 2) * 2;           // c0:0 c1:8 c2:4 c3:12
#pragma unroll
    for (int mt = 0; mt < 2; ++mt) {
#pragma unroll
        for (int h = 0; h < 2; ++h) {
            float2 v0 = make_float2(acc[mt][0][2 * h], acc[mt][0][2 * h + 1]);
            float2 v1 = make_float2(acc[mt][1][2 * h], acc[mt][1][2 * h + 1]);
            // even lanes send nt1, odd lanes send nt0; exchange with lane^1
            float2 snd = (c4 & 1) ? v0 : v1;
            double sd = *reinterpret_cast<double*>(&snd);
            double rd = __shfl_xor_sync(0xffffffffu, sd, 1);
            float2 rcv = *reinterpret_cast<float2*>(&rd);
            float4 res = (c4 & 1) ? make_float4(rcv.x, rcv.y, v1.x, v1.y)
                                  : make_float4(v0.x, v0.y, rcv.x, rcv.y);
            int p  = wbase + mt * 16 + h * 8 + (lane >> 2);
            int jp = (i + dbase + p + 1) & (NPTS - 1);
            __stcs((float4*)(out + ((bb + i) * NPTS + jp) * NH + colbase), res);
            __stcs((float4*)(out + ((bb + jp) * NPTS + i) * NH + colbase), res);
        }
    }
}

extern "C" void kernel_launch(void* const* d_in, const int* in_sizes, int n_in,
                              void* d_out, int out_size) {
    const float* vec_map = (const float*)d_in[0];
    const float* kernelW = (const float*)d_in[1];
    const float* bias    = (const float*)d_in[2];
    float* out = (float*)d_out;

    int total_vecs = in_sizes[0] / 3;   // B * N
    int B = total_vecs / NPTS;

    dim3 grid(NPTS, 2, B);
    relbias_kernel<<<grid, TPB>>>(vec_map, kernelW, bias, out);
}

// round 13
// speedup vs baseline: 1.0318x; 1.0318x over previous
#include <cuda_runtime.h>
#include <cuda_fp16.h>
#include <math.h>
#include <stdint.h>

#define NPTS 1024
#define NH   16
#define WSTRIDE 144  // bytes per sW row: 64 fp16 = 128B + 16B pad (conflict-free)
#define TPB  256

static __device__ __forceinline__ uint32_t smem_addr(const void* p) {
    return (uint32_t)__cvta_generic_to_shared(p);
}

static __device__ __forceinline__ void ldsm_x4(uint32_t& r0, uint32_t& r1,
                                               uint32_t& r2, uint32_t& r3, uint32_t a) {
    asm volatile("ldmatrix.sync.aligned.m8n8.x4.shared.b16 {%0,%1,%2,%3}, [%4];"
                 : "=r"(r0), "=r"(r1), "=r"(r2), "=r"(r3) : "r"(a));
}

static __device__ __forceinline__ void mma16816(float& d0, float& d1, float& d2, float& d3,
                                                uint32_t a0, uint32_t a1, uint32_t a2, uint32_t a3,
                                                uint32_t b0, uint32_t b1) {
    asm volatile("mma.sync.aligned.m16n8k16.row.col.f32.f16.f16.f32 "
                 "{%0,%1,%2,%3}, {%4,%5,%6,%7}, {%8,%9}, {%0,%1,%2,%3};"
                 : "+f"(d0), "+f"(d1), "+f"(d2), "+f"(d3)
                 : "r"(a0), "r"(a1), "r"(a2), "r"(a3), "r"(b0), "r"(b1));
}

// round-to-nearest-even via magic number (valid for |x| < 2^22)
static __device__ __forceinline__ float rne(float x) {
    return (x + 12582912.0f) - 12582912.0f;
}

// Fused kernel, A-fragments built in registers (no A SMEM tile).
// grid = (1024 rows i, 2 d-blocks, B); block = 256 threads; warp owns 32 pairs
// p = wbase+row, j = (i + dbase + wbase + row + 1) mod 1024.
// Lane l (c4=l&3, rq=l>>2) supplies, for rows rq+16mt+{0,8}, the (sin,cos) half2s
// at frequencies c4+4m — generated by rotation chains anchored at c4*t, step 4t,
// exactly matching the m16n8k16 A-fragment layout with interleaved sin/cos features.
// Covers every off-diagonal unordered pair once (distance-512 twice, identical);
// writes out[i,j,:] and out[j,i,:]. Diagonal by d-block 0. Bias in accumulators.
__global__ __launch_bounds__(TPB)
void relbias_kernel(const float* __restrict__ vec,  // [B,1024,3]
                    const float* __restrict__ W,    // [64,16]
                    const float* __restrict__ bias, // [16]
                    float* __restrict__ out) {
    __shared__ __align__(16) uint8_t sW[16 * WSTRIDE];  // fp16 weights [n][f']

    int tid = threadIdx.x;
    int i     = blockIdx.x;
    int dbase = blockIdx.y << 8;
    int b     = blockIdx.z;
    long long bb = (long long)b * NPTS;

    // W[64,16] fp32 -> sW[n][f'] fp16, f' interleaved: f'=2k -> Ws[k], f'=2k+1 -> Wc[k]
    for (int idx = tid; idx < 64 * 16; idx += TPB) {
        int n = idx & 15, k = idx >> 4;
        int fp = (k < 32) ? (2 * k) : (2 * (k - 32) + 1);
        *(__half*)(sW + n * WSTRIDE + fp * 2) = __float2half_rn(W[idx]);
    }
    // diagonal (exact fp32): out[b,i,i,:] = bias + sum_k Wc[k,:]
    if (blockIdx.y == 0 && tid < NH) {
        float a = bias[tid];
#pragma unroll
        for (int k = 0; k < 32; ++k) a += W[(32 + k) * NH + tid];
        out[((bb + i) * NPTS + i) * NH + tid] = a;
    }
    __syncthreads();   // sW ready

    int wid = tid >> 5, lane = tid & 31;
    int wbase = wid << 5;
    int c4 = lane & 3, rq = lane >> 2;

    // B fragments from sW: bfrag[ntile][ktile][2]
    uint32_t bfrag[2][4][2];
    uint32_t sWb = smem_addr(sW);
#pragma unroll
    for (int nt = 0; nt < 2; ++nt) {
#pragma unroll
        for (int ktp = 0; ktp < 2; ++ktp) {
            uint32_t a = sWb + (uint32_t)(nt * 8 + (lane & 7)) * WSTRIDE
                       + (uint32_t)ktp * 64 + (uint32_t)(lane >> 3) * 16;
            ldsm_x4(bfrag[nt][2 * ktp][0], bfrag[nt][2 * ktp][1],
                    bfrag[nt][2 * ktp + 1][0], bfrag[nt][2 * ktp + 1][1], a);
        }
    }

    // normalized i-vector (shared address across block -> L1 broadcast)
    const float* vb = vec + (size_t)b * NPTS * 3;
    float ax = vb[i * 3 + 0], ay = vb[i * 3 + 1], az = vb[i * 3 + 2];
    float ra = rsqrtf(ax * ax + ay * ay + az * az);
    float nix = ax * ra, niy = ay * ra, niz = az * ra;

    float2 bz0 = *(const float2*)(bias + 2 * c4);
    float2 bz1 = *(const float2*)(bias + 8 + 2 * c4);
    int colbase = (c4 & 1) * 8 + (c4 & 2) * 2;        // c0:0 c1:8 c2:4 c3:12
    int jb = i + dbase + wbase + 1;                   // j(row) = (jb + row) & 1023

#pragma unroll
    for (int mt = 0; mt < 2; ++mt) {
        // chain setup for this mt's two rows (rq+16mt, rq+16mt+8)
        float S[2], C[2], SS[2], CC[2];
#pragma unroll
        for (int rr = 0; rr < 2; ++rr) {
            int row = rq + 16 * mt + 8 * rr;
            int j = (jb + row) & (NPTS - 1);
            float bx = vb[j * 3 + 0], by = vb[j * 3 + 1], bz = vb[j * 3 + 2];
            float rb = rsqrtf(bx * bx + by * by + bz * bz);
            float dx = nix - bx * rb;
            float dy = niy - by * rb;
            float dz = niz - bz * rb;
            float dot = 1.0f - 0.5f * ((dx * dx + dy * dy) + dz * dz);
            dot = fminf(fmaxf(dot, -1.0f), 1.0f);
            float t = acosf(dot) * 200.0f * (10.0f / 31.0f);
            // fp32 Cody-Waite mod 2*pi
            float q  = rne(t * 0.15915494309189535f);
            float tr = fmaf(q, -6.28125f, t);
            tr = fmaf(q, -1.9353071795864769e-3f, tr);
            float s1 = __sinf(tr), c1 = __cosf(tr);
            float s2 = 2.0f * s1 * c1;
            float c2 = fmaf(-2.0f * s1, s1, 1.0f);
            float s3 = fmaf(s1, c2, c1 * s2);
            float c3 = fmaf(c1, c2, -(s1 * s2));
            // anchor = sincos(c4 * tr)
            S[rr] = (c4 == 0) ? 0.0f : (c4 == 1) ? s1 : (c4 == 2) ? s2 : s3;
            C[rr] = (c4 == 0) ? 1.0f : (c4 == 1) ? c1 : (c4 == 2) ? c2 : c3;
            // step = sincos(4 * tr)
            SS[rr] = 2.0f * s2 * c2;
            CC[rr] = fmaf(-2.0f * s2, s2, 1.0f);
        }

        // accumulators with bias (acc[nt][e] -> head col nt*8 + 2*c4 + (e&1))
        float acc[2][4];
        acc[0][0] = bz0.x; acc[0][1] = bz0.y; acc[0][2] = bz0.x; acc[0][3] = bz0.y;
        acc[1][0] = bz1.x; acc[1][1] = bz1.y; acc[1][2] = bz1.x; acc[1][3] = bz1.y;

#pragma unroll
        for (int kt = 0; kt < 4; ++kt) {
            uint32_t alo[2], ahi[2];   // (sin,cos) @ freq 8kt+c4 and 8kt+c4+4
#pragma unroll
            for (int rr = 0; rr < 2; ++rr) {
                __half2 h0 = __floats2half2_rn(S[rr], C[rr]);
                alo[rr] = *(uint32_t*)&h0;
                float nS = fmaf(S[rr], CC[rr], C[rr] * SS[rr]);
                float nC = fmaf(C[rr], CC[rr], -(S[rr] * SS[rr]));
                __half2 h1 = __floats2half2_rn(nS, nC);
                ahi[rr] = *(uint32_t*)&h1;
                S[rr] = fmaf(nS, CC[rr], nC * SS[rr]);
                C[rr] = fmaf(nC, CC[rr], -(nS * SS[rr]));
            }
#pragma unroll
            for (int nt = 0; nt < 2; ++nt)
                mma16816(acc[nt][0], acc[nt][1], acc[nt][2], acc[nt][3],
                         alo[0], alo[1], ahi[0], ahi[1],
                         bfrag[nt][kt][0], bfrag[nt][kt][1]);
        }

        // epilogue for this mt: bfly-shuffle into float4, symmetric STG.128
#pragma unroll
        for (int h = 0; h < 2; ++h) {
            float2 v0 = make_float2(acc[0][2 * h], acc[0][2 * h + 1]);
            float2 v1 = make_float2(acc[1][2 * h], acc[1][2 * h + 1]);
            float2 snd = (c4 & 1) ? v0 : v1;
            double sd = *reinterpret_cast<double*>(&snd);
            double rd = __shfl_xor_sync(0xffffffffu, sd, 1);
            float2 rcv = *reinterpret_cast<float2*>(&rd);
            float4 res = (c4 & 1) ? make_float4(rcv.x, rcv.y, v1.x, v1.y)
                                  : make_float4(v0.x, v0.y, rcv.x, rcv.y);
            int p  = wbase + mt * 16 + h * 8 + rq;
            int jp = (i + dbase + p + 1) & (NPTS - 1);
            __stcs((float4*)(out + ((bb + i) * NPTS + jp) * NH + colbase), res);
            __stcs((float4*)(out + ((bb + jp) * NPTS + i) * NH + colbase), res);
        }
    }
}

extern "C" void kernel_launch(void* const* d_in, const int* in_sizes, int n_in,
                              void* d_out, int out_size) {
    const float* vec_map = (const float*)d_in[0];
    const float* kernelW = (const float*)d_in[1];
    const float* bias    = (const float*)d_in[2];
    float* out = (float*)d_out;

    int total_vecs = in_sizes[0] / 3;   // B * N
    int B = total_vecs / NPTS;

    dim3 grid(NPTS, 2, B);
    relbias_kernel<<<grid, TPB>>>(vec_map, kernelW, bias, out);
}

// round 14
// speedup vs baseline: 1.1473x; 1.1120x over previous
#include <cuda_runtime.h>
#include <cuda_fp16.h>
#include <math.h>
#include <stdint.h>

#define NPTS 1024
#define NH   16
#define WSTRIDE 144  // bytes per sW row: 64 fp16 = 128B + 16B pad (conflict-free)
#define TPB  256

static __device__ __forceinline__ uint32_t smem_addr(const void* p) {
    return (uint32_t)__cvta_generic_to_shared(p);
}

static __device__ __forceinline__ void ldsm_x4(uint32_t& r0, uint32_t& r1,
                                               uint32_t& r2, uint32_t& r3, uint32_t a) {
    asm volatile("ldmatrix.sync.aligned.m8n8.x4.shared.b16 {%0,%1,%2,%3}, [%4];"
                 : "=r"(r0), "=r"(r1), "=r"(r2), "=r"(r3) : "r"(a));
}

static __device__ __forceinline__ void mma16816(float& d0, float& d1, float& d2, float& d3,
                                                uint32_t a0, uint32_t a1, uint32_t a2, uint32_t a3,
                                                uint32_t b0, uint32_t b1) {
    asm volatile("mma.sync.aligned.m16n8k16.row.col.f32.f16.f16.f32 "
                 "{%0,%1,%2,%3}, {%4,%5,%6,%7}, {%8,%9}, {%0,%1,%2,%3};"
                 : "+f"(d0), "+f"(d1), "+f"(d2), "+f"(d3)
                 : "r"(a0), "r"(a1), "r"(a2), "r"(a3), "r"(b0), "r"(b1));
}

// round-to-nearest-even via magic number (valid for |x| < 2^22)
static __device__ __forceinline__ float rne(float x) {
    return (x + 12582912.0f) - 12582912.0f;
}

// Fused kernel, A-fragments in registers, lane-specialized angle computation.
// grid = (1024 rows i, 2 d-blocks, B); block = 256 threads; warp owns 32 pairs
// p = wbase+row, j = (i + dbase + wbase + row + 1) mod 1024.
// Lane l computes ONLY row l's angle chain (s1,c1 = sincos(tr), s4,c4s = sincos(4tr));
// consumers shfl row rq+16mt+8rr's 4 values and build their c4-anchor locally.
// Covers every off-diagonal unordered pair once (distance-512 twice, identical);
// writes out[i,j,:] and out[j,i,:]. Diagonal by d-block 0. Bias in accumulators.
__global__ __launch_bounds__(TPB)
void relbias_kernel(const float* __restrict__ vec,  // [B,1024,3]
                    const float* __restrict__ W,    // [64,16]
                    const float* __restrict__ bias, // [16]
                    float* __restrict__ out) {
    __shared__ __align__(16) uint8_t sW[16 * WSTRIDE];  // fp16 weights [n][f']

    int tid = threadIdx.x;
    int i     = blockIdx.x;
    int dbase = blockIdx.y << 8;
    int b     = blockIdx.z;
    uint32_t rowbase = ((uint32_t)b * NPTS + (uint32_t)i) * NPTS;   // (b*N + i)*N

    // W[64,16] fp32 -> sW[n][f'] fp16, f' interleaved: f'=2k -> Ws[k], f'=2k+1 -> Wc[k]
    for (int idx = tid; idx < 64 * 16; idx += TPB) {
        int n = idx & 15, k = idx >> 4;
        int fp = (k < 32) ? (2 * k) : (2 * (k - 32) + 1);
        *(__half*)(sW + n * WSTRIDE + fp * 2) = __float2half_rn(W[idx]);
    }
    // diagonal (exact fp32): out[b,i,i,:] = bias + sum_k Wc[k,:]
    if (blockIdx.y == 0 && tid < NH) {
        float a = bias[tid];
#pragma unroll
        for (int k = 0; k < 32; ++k) a += W[(32 + k) * NH + tid];
        out[(rowbase + (uint32_t)i) * NH + (uint32_t)tid] = a;
    }
    __syncthreads();   // sW ready

    int wid = tid >> 5, lane = tid & 31;
    int wbase = wid << 5;
    int c4 = lane & 3, rq = lane >> 2;

    // B fragments from sW: bfrag[ntile][ktile][2]
    uint32_t bfrag[2][4][2];
    uint32_t sWb = smem_addr(sW);
#pragma unroll
    for (int nt = 0; nt < 2; ++nt) {
#pragma unroll
        for (int ktp = 0; ktp < 2; ++ktp) {
            uint32_t a = sWb + (uint32_t)(nt * 8 + (lane & 7)) * WSTRIDE
                       + (uint32_t)ktp * 64 + (uint32_t)(lane >> 3) * 16;
            ldsm_x4(bfrag[nt][2 * ktp][0], bfrag[nt][2 * ktp][1],
                    bfrag[nt][2 * ktp + 1][0], bfrag[nt][2 * ktp + 1][1], a);
        }
    }

    // ---- lane-specialized: this lane computes row = lane's angle chain ----
    const float* vb = vec + (uint32_t)b * (NPTS * 3);
    float ax = vb[i * 3 + 0], ay = vb[i * 3 + 1], az = vb[i * 3 + 2];
    float ra = rsqrtf(ax * ax + ay * ay + az * az);
    float nix = ax * ra, niy = ay * ra, niz = az * ra;

    int jb = i + dbase + wbase + 1;                 // j(row) = (jb + row) & 1023
    float s1, c1, s4, c4s;
    {
        int jo = (jb + lane) & (NPTS - 1);
        float bx = vb[jo * 3 + 0], by = vb[jo * 3 + 1], bz = vb[jo * 3 + 2];
        float rb = rsqrtf(bx * bx + by * by + bz * bz);
        float dx = nix - bx * rb;
        float dy = niy - by * rb;
        float dz = niz - bz * rb;
        float dot = 1.0f - 0.5f * ((dx * dx + dy * dy) + dz * dz);
        dot = fminf(fmaxf(dot, -1.0f), 1.0f);
        float t = acosf(dot) * 200.0f * (10.0f / 31.0f);
        // fp32 Cody-Waite mod 2*pi
        float q  = rne(t * 0.15915494309189535f);
        float tr = fmaf(q, -6.28125f, t);
        tr = fmaf(q, -1.9353071795864769e-3f, tr);
        s1 = __sinf(tr);
        c1 = __cosf(tr);
        float s2 = 2.0f * s1 * c1;
        float c2 = fmaf(-2.0f * s1, s1, 1.0f);
        s4  = 2.0f * s2 * c2;                       // sincos(4*tr)
        c4s = fmaf(-2.0f * s2, s2, 1.0f);
    }

    float2 bz0 = *(const float2*)(bias + 2 * c4);
    float2 bz1 = *(const float2*)(bias + 8 + 2 * c4);
    int colbase = (c4 & 1) * 8 + (c4 & 2) * 2;      // c0:0 c1:8 c2:4 c3:12

#pragma unroll
    for (int mt = 0; mt < 2; ++mt) {
        // fetch the two consumed rows' chain data via shuffle; build c4-anchor locally
        float S[2], C[2], SS[2], CC[2];
#pragma unroll
        for (int rr = 0; rr < 2; ++rr) {
            int row = rq + 16 * mt + 8 * rr;
            float s1r = __shfl_sync(0xffffffffu, s1, row);
            float c1r = __shfl_sync(0xffffffffu, c1, row);
            SS[rr] = __shfl_sync(0xffffffffu, s4, row);
            CC[rr] = __shfl_sync(0xffffffffu, c4s, row);
            float s2r = 2.0f * s1r * c1r;
            float c2r = fmaf(-2.0f * s1r, s1r, 1.0f);
            float s3r = fmaf(s1r, c2r, c1r * s2r);
            float c3r = fmaf(c1r, c2r, -(s1r * s2r));
            S[rr] = (c4 == 0) ? 0.0f : (c4 == 1) ? s1r : (c4 == 2) ? s2r : s3r;
            C[rr] = (c4 == 0) ? 1.0f : (c4 == 1) ? c1r : (c4 == 2) ? c2r : c3r;
        }

        // accumulators with bias (acc[nt][e] -> head col nt*8 + 2*c4 + (e&1))
        float acc[2][4];
        acc[0][0] = bz0.x; acc[0][1] = bz0.y; acc[0][2] = bz0.x; acc[0][3] = bz0.y;
        acc[1][0] = bz1.x; acc[1][1] = bz1.y; acc[1][2] = bz1.x; acc[1][3] = bz1.y;

#pragma unroll
        for (int kt = 0; kt < 4; ++kt) {
            uint32_t alo[2], ahi[2];   // (sin,cos) @ freq 8kt+c4 and 8kt+c4+4
#pragma unroll
            for (int rr = 0; rr < 2; ++rr) {
                __half2 h0 = __floats2half2_rn(S[rr], C[rr]);
                alo[rr] = *(uint32_t*)&h0;
                float nS = fmaf(S[rr], CC[rr], C[rr] * SS[rr]);
                float nC = fmaf(C[rr], CC[rr], -(S[rr] * SS[rr]));
                __half2 h1 = __floats2half2_rn(nS, nC);
                ahi[rr] = *(uint32_t*)&h1;
                S[rr] = fmaf(nS, CC[rr], nC * SS[rr]);
                C[rr] = fmaf(nC, CC[rr], -(nS * SS[rr]));
            }
#pragma unroll
            for (int nt = 0; nt < 2; ++nt)
                mma16816(acc[nt][0], acc[nt][1], acc[nt][2], acc[nt][3],
                         alo[0], alo[1], ahi[0], ahi[1],
                         bfrag[nt][kt][0], bfrag[nt][kt][1]);
        }

        // epilogue: bfly-shuffle into float4, symmetric STG.128 (32-bit addressing)
#pragma unroll
        for (int h = 0; h < 2; ++h) {
            float2 v0 = make_float2(acc[0][2 * h], acc[0][2 * h + 1]);
            float2 v1 = make_float2(acc[1][2 * h], acc[1][2 * h + 1]);
            float2 snd = (c4 & 1) ? v0 : v1;
            double sd = *reinterpret_cast<double*>(&snd);
            double rd = __shfl_xor_sync(0xffffffffu, sd, 1);
            float2 rcv = *reinterpret_cast<float2*>(&rd);
            float4 res = (c4 & 1) ? make_float4(rcv.x, rcv.y, v1.x, v1.y)
                                  : make_float4(v0.x, v0.y, rcv.x, rcv.y);
            int p  = wbase + mt * 16 + h * 8 + rq;
            uint32_t jp = (uint32_t)((i + dbase + p + 1) & (NPTS - 1));
            uint32_t oi = (rowbase + jp) * NH + (uint32_t)colbase;
            uint32_t oj = (((uint32_t)b * NPTS + jp) * NPTS + (uint32_t)i) * NH
                        + (uint32_t)colbase;
            __stcs((float4*)(out + oi), res);
            __stcs((float4*)(out + oj), res);
        }
    }
}

extern "C" void kernel_launch(void* const* d_in, const int* in_sizes, int n_in,
                              void* d_out, int out_size) {
    const float* vec_map = (const float*)d_in[0];
    const float* kernelW = (const float*)d_in[1];
    const float* bias    = (const float*)d_in[2];
    float* out = (float*)d_out;

    int total_vecs = in_sizes[0] / 3;   // B * N
    int B = total_vecs / NPTS;

    dim3 grid(NPTS, 2, B);
    relbias_kernel<<<grid, TPB>>>(vec_map, kernelW, bias, out);
}

// round 15
// speedup vs baseline: 1.2006x; 1.0465x over previous
#include <cuda_runtime.h>
#include <cuda_fp16.h>
#include <math.h>
#include <stdint.h>

#define NPTS 1024
#define NH   16
#define WSTRIDE 144  // bytes per sW row: 64 fp16 = 128B + 16B pad (conflict-free)
#define TPB  256

static __device__ __forceinline__ uint32_t smem_addr(const void* p) {
    return (uint32_t)__cvta_generic_to_shared(p);
}

static __device__ __forceinline__ void ldsm_x4(uint32_t& r0, uint32_t& r1,
                                               uint32_t& r2, uint32_t& r3, uint32_t a) {
    asm volatile("ldmatrix.sync.aligned.m8n8.x4.shared.b16 {%0,%1,%2,%3}, [%4];"
                 : "=r"(r0), "=r"(r1), "=r"(r2), "=r"(r3) : "r"(a));
}

static __device__ __forceinline__ void mma16816(float& d0, float& d1, float& d2, float& d3,
                                                uint32_t a0, uint32_t a1, uint32_t a2, uint32_t a3,
                                                uint32_t b0, uint32_t b1) {
    asm volatile("mma.sync.aligned.m16n8k16.row.col.f32.f16.f16.f32 "
                 "{%0,%1,%2,%3}, {%4,%5,%6,%7}, {%8,%9}, {%0,%1,%2,%3};"
                 : "+f"(d0), "+f"(d1), "+f"(d2), "+f"(d3)
                 : "r"(a0), "r"(a1), "r"(a2), "r"(a3), "r"(b0), "r"(b1));
}

// round-to-nearest-even via magic number (valid for |x| < 2^22)
static __device__ __forceinline__ float rne(float x) {
    return (x + 12582912.0f) - 12582912.0f;
}

// Fused kernel: A-fragments in registers, lane-specialized angles, Chebyshev chains.
// grid = (1024 rows i, 2 d-blocks, B); block = 256 threads; warp owns 32 pairs
// p = wbase+row, j = (i + dbase + wbase + row + 1) mod 1024.
// Lane l computes ONLY row l's angle chain (s1,c1 = sincos(tr), s4,c4s = sincos(4tr));
// consumers shfl row rq+16mt+8rr's values, anchor at c4*t, then generate the 8
// needed (sin,cos) points at freqs c4+4m via the Chebyshev second-order recurrence
// x_{m+1} = 2*cos(4t)*x_m - x_{m-1}  (1 FMA per value).
// Covers every off-diagonal unordered pair once (distance-512 twice, identical);
// writes out[i,j,:] and out[j,i,:]. Diagonal by d-block 0. Bias in accumulators.
__global__ __launch_bounds__(TPB, 4)
void relbias_kernel(const float* __restrict__ vec,  // [B,1024,3]
                    const float* __restrict__ W,    // [64,16]
                    const float* __restrict__ bias, // [16]
                    float* __restrict__ out) {
    __shared__ __align__(16) uint8_t sW[16 * WSTRIDE];  // fp16 weights [n][f']

    int tid = threadIdx.x;
    int i     = blockIdx.x;
    int dbase = blockIdx.y << 8;
    int b     = blockIdx.z;
    uint32_t rowbase = ((uint32_t)b * NPTS + (uint32_t)i) * NPTS;   // (b*N + i)*N

    // W[64,16] fp32 -> sW[n][f'] fp16, f' interleaved: f'=2k -> Ws[k], f'=2k+1 -> Wc[k]
    for (int idx = tid; idx < 64 * 16; idx += TPB) {
        int n = idx & 15, k = idx >> 4;
        int fp = (k < 32) ? (2 * k) : (2 * (k - 32) + 1);
        *(__half*)(sW + n * WSTRIDE + fp * 2) = __float2half_rn(W[idx]);
    }
    // diagonal (exact fp32): out[b,i,i,:] = bias + sum_k Wc[k,:]
    if (blockIdx.y == 0 && tid < NH) {
        float a = bias[tid];
#pragma unroll
        for (int k = 0; k < 32; ++k) a += W[(32 + k) * NH + tid];
        out[(rowbase + (uint32_t)i) * NH + (uint32_t)tid] = a;
    }
    __syncthreads();   // sW ready

    int wid = tid >> 5, lane = tid & 31;
    int wbase = wid << 5;
    int c4 = lane & 3, rq = lane >> 2;

    // B fragments from sW: bfrag[ntile][ktile][2]
    uint32_t bfrag[2][4][2];
    uint32_t sWb = smem_addr(sW);
#pragma unroll
    for (int nt = 0; nt < 2; ++nt) {
#pragma unroll
        for (int ktp = 0; ktp < 2; ++ktp) {
            uint32_t a = sWb + (uint32_t)(nt * 8 + (lane & 7)) * WSTRIDE
                       + (uint32_t)ktp * 64 + (uint32_t)(lane >> 3) * 16;
            ldsm_x4(bfrag[nt][2 * ktp][0], bfrag[nt][2 * ktp][1],
                    bfrag[nt][2 * ktp + 1][0], bfrag[nt][2 * ktp + 1][1], a);
        }
    }

    // ---- lane-specialized: this lane computes row = lane's angle chain ----
    const float* vb = vec + (uint32_t)b * (NPTS * 3);
    float ax = vb[i * 3 + 0], ay = vb[i * 3 + 1], az = vb[i * 3 + 2];
    float ra = rsqrtf(ax * ax + ay * ay + az * az);
    float nix = ax * ra, niy = ay * ra, niz = az * ra;

    int jb = i + dbase + wbase + 1;                 // j(row) = (jb + row) & 1023
    float s1, c1, s4, c4s;
    {
        int jo = (jb + lane) & (NPTS - 1);
        float bx = vb[jo * 3 + 0], by = vb[jo * 3 + 1], bz = vb[jo * 3 + 2];
        float rb = rsqrtf(bx * bx + by * by + bz * bz);
        float dx = nix - bx * rb;
        float dy = niy - by * rb;
        float dz = niz - bz * rb;
        float dot = 1.0f - 0.5f * ((dx * dx + dy * dy) + dz * dz);
        dot = fminf(fmaxf(dot, -1.0f), 1.0f);
        float t = acosf(dot) * 200.0f * (10.0f / 31.0f);
        // fp32 Cody-Waite mod 2*pi
        float q  = rne(t * 0.15915494309189535f);
        float tr = fmaf(q, -6.28125f, t);
        tr = fmaf(q, -1.9353071795864769e-3f, tr);
        s1 = __sinf(tr);
        c1 = __cosf(tr);
        float s2 = 2.0f * s1 * c1;
        float c2 = fmaf(-2.0f * s1, s1, 1.0f);
        s4  = 2.0f * s2 * c2;                       // sincos(4*tr)
        c4s = fmaf(-2.0f * s2, s2, 1.0f);
    }

    float2 bz0 = *(const float2*)(bias + 2 * c4);
    float2 bz1 = *(const float2*)(bias + 8 + 2 * c4);
    int colbase = (c4 & 1) * 8 + (c4 & 2) * 2;      // c0:0 c1:8 c2:4 c3:12

#pragma unroll
    for (int mt = 0; mt < 2; ++mt) {
        // generate 8 fragment half2s per consumed row via anchor + Chebyshev
        uint32_t frag[2][8];
#pragma unroll
        for (int rr = 0; rr < 2; ++rr) {
            int row = rq + 16 * mt + 8 * rr;
            float s1r = __shfl_sync(0xffffffffu, s1, row);
            float c1r = __shfl_sync(0xffffffffu, c1, row);
            float SS  = __shfl_sync(0xffffffffu, s4, row);
            float CC  = __shfl_sync(0xffffffffu, c4s, row);
            float s2r = 2.0f * s1r * c1r;
            float c2r = fmaf(-2.0f * s1r, s1r, 1.0f);
            float s3r = fmaf(s1r, c2r, c1r * s2r);
            float c3r = fmaf(c1r, c2r, -(s1r * s2r));
            float S0 = (c4 == 0) ? 0.0f : (c4 == 1) ? s1r : (c4 == 2) ? s2r : s3r;
            float C0 = (c4 == 0) ? 1.0f : (c4 == 1) ? c1r : (c4 == 2) ? c2r : c3r;
            float S1 = fmaf(S0, CC, C0 * SS);
            float C1 = fmaf(C0, CC, -(S0 * SS));
            float twoCC = CC + CC;
            __half2 h0 = __floats2half2_rn(S0, C0);
            __half2 h1 = __floats2half2_rn(S1, C1);
            frag[rr][0] = *(uint32_t*)&h0;
            frag[rr][1] = *(uint32_t*)&h1;
            float Sp = S0, Sc = S1, Cp = C0, Cc = C1;
#pragma unroll
            for (int m = 2; m < 8; ++m) {
                float Sn = fmaf(twoCC, Sc, -Sp);
                float Cn = fmaf(twoCC, Cc, -Cp);
                __half2 hm = __floats2half2_rn(Sn, Cn);
                frag[rr][m] = *(uint32_t*)&hm;
                Sp = Sc; Sc = Sn; Cp = Cc; Cc = Cn;
            }
        }

        // accumulators with bias (acc[nt][e] -> head col nt*8 + 2*c4 + (e&1))
        float acc[2][4];
        acc[0][0] = bz0.x; acc[0][1] = bz0.y; acc[0][2] = bz0.x; acc[0][3] = bz0.y;
        acc[1][0] = bz1.x; acc[1][1] = bz1.y; acc[1][2] = bz1.x; acc[1][3] = bz1.y;

#pragma unroll
        for (int kt = 0; kt < 4; ++kt) {
#pragma unroll
            for (int nt = 0; nt < 2; ++nt)
                mma16816(acc[nt][0], acc[nt][1], acc[nt][2], acc[nt][3],
                         frag[0][2 * kt], frag[1][2 * kt],
                         frag[0][2 * kt + 1], frag[1][2 * kt + 1],
                         bfrag[nt][kt][0], bfrag[nt][kt][1]);
        }

        // epilogue: bfly-shuffle into float4, symmetric STG.128 (32-bit addressing)
#pragma unroll
        for (int h = 0; h < 2; ++h) {
            float2 v0 = make_float2(acc[0][2 * h], acc[0][2 * h + 1]);
            float2 v1 = make_float2(acc[1][2 * h], acc[1][2 * h + 1]);
            float2 snd = (c4 & 1) ? v0 : v1;
            double sd = *reinterpret_cast<double*>(&snd);
            double rd = __shfl_xor_sync(0xffffffffu, sd, 1);
            float2 rcv = *reinterpret_cast<float2*>(&rd);
            float4 res = (c4 & 1) ? make_float4(rcv.x, rcv.y, v1.x, v1.y)
                                  : make_float4(v0.x, v0.y, rcv.x, rcv.y);
            int p  = wbase + mt * 16 + h * 8 + rq;
            uint32_t jp = (uint32_t)((i + dbase + p + 1) & (NPTS - 1));
            uint32_t oi = (rowbase + jp) * NH + (uint32_t)colbase;
            uint32_t oj = (((uint32_t)b * NPTS + jp) * NPTS + (uint32_t)i) * NH
                        + (uint32_t)colbase;
            __stcs((float4*)(out + oi), res);
            __stcs((float4*)(out + oj), res);
        }
    }
}

extern "C" void kernel_launch(void* const* d_in, const int* in_sizes, int n_in,
                              void* d_out, int out_size) {
    const float* vec_map = (const float*)d_in[0];
    const float* kernelW = (const float*)d_in[1];
    const float* bias    = (const float*)d_in[2];
    float* out = (float*)d_out;

    int total_vecs = in_sizes[0] / 3;   // B * N
    int B = total_vecs / NPTS;

    dim3 grid(NPTS, 2, B);
    relbias_kernel<<<grid, TPB>>>(vec_map, kernelW, bias, out);
}

// round 16
// speedup vs baseline: 1.3408x; 1.1167x over previous
#include <cuda_runtime.h>
#include <cuda_fp16.h>
#include <math.h>
#include <stdint.h>

#define NPTS 1024
#define NH   16
#define WSTRIDE 144  // bytes per sW row: 64 fp16 = 128B + 16B pad (conflict-free)
#define TPB  256

static __device__ __forceinline__ uint32_t smem_addr(const void* p) {
    return (uint32_t)__cvta_generic_to_shared(p);
}

static __device__ __forceinline__ void ldsm_x4(uint32_t& r0, uint32_t& r1,
                                               uint32_t& r2, uint32_t& r3, uint32_t a) {
    asm volatile("ldmatrix.sync.aligned.m8n8.x4.shared.b16 {%0,%1,%2,%3}, [%4];"
                 : "=r"(r0), "=r"(r1), "=r"(r2), "=r"(r3) : "r"(a));
}

static __device__ __forceinline__ void mma16816(float& d0, float& d1, float& d2, float& d3,
                                                uint32_t a0, uint32_t a1, uint32_t a2, uint32_t a3,
                                                uint32_t b0, uint32_t b1) {
    asm volatile("mma.sync.aligned.m16n8k16.row.col.f32.f16.f16.f32 "
                 "{%0,%1,%2,%3}, {%4,%5,%6,%7}, {%8,%9}, {%0,%1,%2,%3};"
                 : "+f"(d0), "+f"(d1), "+f"(d2), "+f"(d3)
                 : "r"(a0), "r"(a1), "r"(a2), "r"(a3), "r"(b0), "r"(b1));
}

// round-to-nearest-even via magic number (valid for |x| < 2^22)
static __device__ __forceinline__ float rne(float x) {
    return (x + 12582912.0f) - 12582912.0f;
}

// Fused kernel: A-fragments in registers, lane-specialized angles, Chebyshev chains,
// 4 pairs per thread (prologue amortized 2x vs R15).
// grid = (1024 rows i, 1, B); block = 256 threads; warp owns 64 pairs:
// offsets d = wbase*2 + {lane, lane+32}, j = (i + d + 1) mod 1024.
// Lane l computes chains for its two offsets; the mt loop runs 4 row-groups
// (0-31 from chain A, 32-63 from chain B) of the proven R15 structure.
// Covers every off-diagonal unordered pair once (distance-512 twice, identical);
// writes out[i,j,:] and out[j,i,:]. Diagonal by every block (i row). Bias in accs.
__global__ __launch_bounds__(TPB, 4)
void relbias_kernel(const float* __restrict__ vec,  // [B,1024,3]
                    const float* __restrict__ W,    // [64,16]
                    const float* __restrict__ bias, // [16]
                    float* __restrict__ out) {
    __shared__ __align__(16) uint8_t sW[16 * WSTRIDE];  // fp16 weights [n][f']

    int tid = threadIdx.x;
    int i = blockIdx.x;
    int b = blockIdx.y;
    uint32_t rowbase = ((uint32_t)b * NPTS + (uint32_t)i) * NPTS;   // (b*N + i)*N

    // W[64,16] fp32 -> sW[n][f'] fp16, f' interleaved: f'=2k -> Ws[k], f'=2k+1 -> Wc[k]
    for (int idx = tid; idx < 64 * 16; idx += TPB) {
        int n = idx & 15, k = idx >> 4;
        int fp = (k < 32) ? (2 * k) : (2 * (k - 32) + 1);
        *(__half*)(sW + n * WSTRIDE + fp * 2) = __float2half_rn(W[idx]);
    }
    // diagonal (exact fp32): out[b,i,i,:] = bias + sum_k Wc[k,:]
    if (tid < NH) {
        float a = bias[tid];
#pragma unroll
        for (int k = 0; k < 32; ++k) a += W[(32 + k) * NH + tid];
        out[(rowbase + (uint32_t)i) * NH + (uint32_t)tid] = a;
    }
    __syncthreads();   // sW ready

    int wid = tid >> 5, lane = tid & 31;
    int dstart = wid << 6;                      // 64 offsets per warp
    int c4 = lane & 3, rq = lane >> 2;

    // B fragments from sW: bfrag[ntile][ktile][2]
    uint32_t bfrag[2][4][2];
    uint32_t sWb = smem_addr(sW);
#pragma unroll
    for (int nt = 0; nt < 2; ++nt) {
#pragma unroll
        for (int ktp = 0; ktp < 2; ++ktp) {
            uint32_t a = sWb + (uint32_t)(nt * 8 + (lane & 7)) * WSTRIDE
                       + (uint32_t)ktp * 64 + (uint32_t)(lane >> 3) * 16;
            ldsm_x4(bfrag[nt][2 * ktp][0], bfrag[nt][2 * ktp][1],
                    bfrag[nt][2 * ktp + 1][0], bfrag[nt][2 * ktp + 1][1], a);
        }
    }

    // normalized i-vector
    const float* vb = vec + (uint32_t)b * (NPTS * 3);
    float ax = vb[i * 3 + 0], ay = vb[i * 3 + 1], az = vb[i * 3 + 2];
    float ra = rsqrtf(ax * ax + ay * ay + az * az);
    float nix = ax * ra, niy = ay * ra, niz = az * ra;

    int jb = i + dstart + 1;                    // j(off) = (jb + off) & 1023

    // ---- lane-specialized: two chains, offsets lane and lane+32 ----
    float s1A, c1A, s4A, c4sA, s1B, c1B, s4B, c4sB;
#pragma unroll
    for (int cb = 0; cb < 2; ++cb) {
        int jo = (jb + lane + 32 * cb) & (NPTS - 1);
        float bx = vb[jo * 3 + 0], by = vb[jo * 3 + 1], bz = vb[jo * 3 + 2];
        float rb = rsqrtf(bx * bx + by * by + bz * bz);
        float dx = nix - bx * rb;
        float dy = niy - by * rb;
        float dz = niz - bz * rb;
        float dot = 1.0f - 0.5f * ((dx * dx + dy * dy) + dz * dz);
        dot = fminf(fmaxf(dot, -1.0f), 1.0f);
        float t = acosf(dot) * 200.0f * (10.0f / 31.0f);
        float q  = rne(t * 0.15915494309189535f);
        float tr = fmaf(q, -6.28125f, t);
        tr = fmaf(q, -1.9353071795864769e-3f, tr);
        float s1 = __sinf(tr), c1 = __cosf(tr);
        float s2 = 2.0f * s1 * c1;
        float c2 = fmaf(-2.0f * s1, s1, 1.0f);
        float s4 = 2.0f * s2 * c2;
        float c4v = fmaf(-2.0f * s2, s2, 1.0f);
        if (cb == 0) { s1A = s1; c1A = c1; s4A = s4; c4sA = c4v; }
        else         { s1B = s1; c1B = c1; s4B = s4; c4sB = c4v; }
    }

    float2 bz0 = *(const float2*)(bias + 2 * c4);
    float2 bz1 = *(const float2*)(bias + 8 + 2 * c4);
    int colbase = (c4 & 1) * 8 + (c4 & 2) * 2;  // c0:0 c1:8 c2:4 c3:12

#pragma unroll
    for (int g = 0; g < 4; ++g) {               // row-group: rows 16g .. 16g+15 (of 64)
        int cb = g >> 1;                        // chain select
        int mt = g & 1;
        float s1v = cb ? s1B : s1A;
        float c1v = cb ? c1B : c1A;
        float s4v = cb ? s4B : s4A;
        float c4sv = cb ? c4sB : c4sA;

        // generate 8 fragment half2s per consumed row via anchor + Chebyshev
        uint32_t frag[2][8];
#pragma unroll
        for (int rr = 0; rr < 2; ++rr) {
            int row = rq + 16 * mt + 8 * rr;    // 0..31 within chain
            float s1r = __shfl_sync(0xffffffffu, s1v, row);
            float c1r = __shfl_sync(0xffffffffu, c1v, row);
            float SS  = __shfl_sync(0xffffffffu, s4v, row);
            float CC  = __shfl_sync(0xffffffffu, c4sv, row);
            float s2r = 2.0f * s1r * c1r;
            float c2r = fmaf(-2.0f * s1r, s1r, 1.0f);
            float s3r = fmaf(s1r, c2r, c1r * s2r);
            float c3r = fmaf(c1r, c2r, -(s1r * s2r));
            float S0 = (c4 == 0) ? 0.0f : (c4 == 1) ? s1r : (c4 == 2) ? s2r : s3r;
            float C0 = (c4 == 0) ? 1.0f : (c4 == 1) ? c1r : (c4 == 2) ? c2r : c3r;
            float S1 = fmaf(S0, CC, C0 * SS);
            float C1 = fmaf(C0, CC, -(S0 * SS));
            float twoCC = CC + CC;
            __half2 h0 = __floats2half2_rn(S0, C0);
            __half2 h1 = __floats2half2_rn(S1, C1);
            frag[rr][0] = *(uint32_t*)&h0;
            frag[rr][1] = *(uint32_t*)&h1;
            float Sp = S0, Sc = S1, Cp = C0, Cc = C1;
#pragma unroll
            for (int m = 2; m < 8; ++m) {
                float Sn = fmaf(twoCC, Sc, -Sp);
                float Cn = fmaf(twoCC, Cc, -Cp);
                __half2 hm = __floats2half2_rn(Sn, Cn);
                frag[rr][m] = *(uint32_t*)&hm;
                Sp = Sc; Sc = Sn; Cp = Cc; Cc = Cn;
            }
        }

        // accumulators with bias (acc[nt][e] -> head col nt*8 + 2*c4 + (e&1))
        float acc[2][4];
        acc[0][0] = bz0.x; acc[0][1] = bz0.y; acc[0][2] = bz0.x; acc[0][3] = bz0.y;
        acc[1][0] = bz1.x; acc[1][1] = bz1.y; acc[1][2] = bz1.x; acc[1][3] = bz1.y;

#pragma unroll
        for (int kt = 0; kt < 4; ++kt) {
#pragma unroll
            for (int nt = 0; nt < 2; ++nt)
                mma16816(acc[nt][0], acc[nt][1], acc[nt][2], acc[nt][3],
                         frag[0][2 * kt], frag[1][2 * kt],
                         frag[0][2 * kt + 1], frag[1][2 * kt + 1],
                         bfrag[nt][kt][0], bfrag[nt][kt][1]);
        }

        // epilogue: bfly-shuffle into float4, symmetric STG.128 (32-bit addressing)
#pragma unroll
        for (int h = 0; h < 2; ++h) {
            float2 v0 = make_float2(acc[0][2 * h], acc[0][2 * h + 1]);
            float2 v1 = make_float2(acc[1][2 * h], acc[1][2 * h + 1]);
            float2 snd = (c4 & 1) ? v0 : v1;
            double sd = *reinterpret_cast<double*>(&snd);
            double rd = __shfl_xor_sync(0xffffffffu, sd, 1);
            float2 rcv = *reinterpret_cast<float2*>(&rd);
            float4 res = (c4 & 1) ? make_float4(rcv.x, rcv.y, v1.x, v1.y)
                                  : make_float4(v0.x, v0.y, rcv.x, rcv.y);
            int off = 32 * cb + mt * 16 + h * 8 + rq;       // 0..63 within warp
            uint32_t jp = (uint32_t)((jb + off) & (NPTS - 1));
            uint32_t oi = (rowbase + jp) * NH + (uint32_t)colbase;
            uint32_t oj = (((uint32_t)b * NPTS + jp) * NPTS + (uint32_t)i) * NH
                        + (uint32_t)colbase;
            __stcs((float4*)(out + oi), res);
            __stcs((float4*)(out + oj), res);
        }
    }
}

extern "C" void kernel_launch(void* const* d_in, const int* in_sizes, int n_in,
                              void* d_out, int out_size) {
    const float* vec_map = (const float*)d_in[0];
    const float* kernelW = (const float*)d_in[1];
    const float* bias    = (const float*)d_in[2];
    float* out = (float*)d_out;

    int total_vecs = in_sizes[0] / 3;   // B * N
    int B = total_vecs / NPTS;

    dim3 grid(NPTS, B);
    relbias_kernel<<<grid, TPB>>>(vec_map, kernelW, bias, out);
}